// round 12
// baseline (speedup 1.0000x reference)
#include <cuda_runtime.h>
#include <cuda_bf16.h>
#include <cstdint>
#include <cstddef>

// ---------------------------------------------------------------------------
// AttentionLePE: x[8,32,32,512] -> qkv GEMM -> 16-head attention (d=32)
//                + 5x5 depthwise conv (LePE) -> proj GEMM + bias
// Round 11: 2-stage cp.async software pipelines in both the GEMM (BK=16,
// double-buffered, one sync per chunk) and the attention kv-loop.
// ---------------------------------------------------------------------------

#define BATCH 8
#define HH 32
#define WW 32
#define DIM 512
#define NHEADS 16
#define HD 32
#define NTOK 1024              // HH*WW
#define M_ROWS (BATCH * NTOK)  // 8192
#define C3 (3 * DIM)           // 1536

__device__ float g_qkv[(size_t)M_ROWS * C3];   // 50.3 MB
__device__ float g_ao[(size_t)M_ROWS * DIM];   // 16.8 MB (attn out + lepe)

__device__ __forceinline__ uint32_t smem_u32(const void* p) {
    uint32_t a;
    asm("{ .reg .u64 t; cvta.to.shared.u64 t, %1; cvt.u32.u64 %0, t; }"
        : "=r"(a) : "l"(p));
    return a;
}

__device__ __forceinline__ void cp_async16(uint32_t saddr, const void* gaddr) {
    asm volatile("cp.async.cg.shared.global [%0], [%1], 16;"
                 :: "r"(saddr), "l"(gaddr));
}
__device__ __forceinline__ void cp_commit() {
    asm volatile("cp.async.commit_group;");
}
__device__ __forceinline__ void cp_wait0() {
    asm volatile("cp.async.wait_group 0;" ::: "memory");
}

__device__ __forceinline__ uint32_t cvt_tf32(float f) {
    uint32_t r;
    asm("cvt.rna.tf32.f32 %0, %1;" : "=r"(r) : "f"(f));
    return r;
}

__device__ __forceinline__ void mma_tf32(
    float c[4], uint32_t a0, uint32_t a1, uint32_t a2, uint32_t a3,
    uint32_t b0, uint32_t b1)
{
    asm volatile(
        "mma.sync.aligned.m16n8k8.row.col.f32.tf32.tf32.f32 "
        "{%0,%1,%2,%3}, {%4,%5,%6,%7}, {%8,%9}, {%0,%1,%2,%3};"
        : "+f"(c[0]), "+f"(c[1]), "+f"(c[2]), "+f"(c[3])
        : "r"(a0), "r"(a1), "r"(a2), "r"(a3), "r"(b0), "r"(b1));
}

// ---------------------------------------------------------------------------
// mma.sync tf32 TN GEMM, 2-stage cp.async pipeline.
// Block 128x128, BK=16 double-buffered, 8 warps (2x4), warp tile 64x32.
// Padded stride 20 floats -> fragment LDS (20g+tg) mod 32 conflict-free.
// tf32 conversion at fragment read (fill path is pure cp.async).
// ---------------------------------------------------------------------------
#define BKF 16
#define BKP2 20

__global__ __launch_bounds__(256) void gemm_mma(
    const float* __restrict__ A, const float* __restrict__ B,
    const float* __restrict__ bias, float* __restrict__ C,
    int N, int K)
{
    __shared__ float sA[2][128 * BKP2];
    __shared__ float sB[2][128 * BKP2];

    const int t = threadIdx.x;
    const int wid = t >> 5;
    const int lane = t & 31;
    const int wm = wid >> 2;        // 0..1  (warp row)
    const int wn = wid & 3;         // 0..3  (warp col)
    const int g = lane >> 2;        // groupID 0..7
    const int tg = lane & 3;        // thread-in-group 0..3
    const int bm = blockIdx.y * 128;
    const int bn = blockIdx.x * 128;

    const uint32_t sa0 = smem_u32(&sA[0][0]);
    const uint32_t sb0 = smem_u32(&sB[0][0]);
    const int pr = t >> 1;                // row 0..127 (2 threads per row)
    const int pc = (t & 1) * 2;           // first float4 index (0 or 2)
    const float* Ag = A + (size_t)(bm + pr) * K + pc * 4;
    const float* Bg = B + (size_t)(bn + pr) * K + pc * 4;
    const uint32_t sAo = (uint32_t)(pr * BKP2 + pc * 4) * 4u;
    const uint32_t sBo = sAo;
    const uint32_t bufstride = 128 * BKP2 * 4u;

    float c[16][4];
#pragma unroll
    for (int i = 0; i < 16; i++)
#pragma unroll
        for (int j = 0; j < 4; j++) c[i][j] = 0.f;

    const int nchunk = K >> 4;      // K/16

    // prefetch chunk 0 -> buf 0
#pragma unroll
    for (int j = 0; j < 2; j++) {
        cp_async16(sa0 + sAo + j * 16u, Ag + j * 4);
        cp_async16(sb0 + sBo + j * 16u, Bg + j * 4);
    }
    cp_commit();

    for (int ch = 0; ch < nchunk; ch++) {
        cp_wait0();
        __syncthreads();
        if (ch + 1 < nchunk) {
            const uint32_t bo = ((ch + 1) & 1) * bufstride;
            const int kb = (ch + 1) * BKF;
#pragma unroll
            for (int j = 0; j < 2; j++) {
                cp_async16(sa0 + bo + sAo + j * 16u, Ag + kb + j * 4);
                cp_async16(sb0 + bo + sBo + j * 16u, Bg + kb + j * 4);
            }
            cp_commit();
        }

        const float* a = sA[ch & 1];
        const float* bsh = sB[ch & 1];
#pragma unroll
        for (int ks = 0; ks < 2; ks++) {
            const int k0 = ks * 8;
            uint32_t af[4][4];
#pragma unroll
            for (int mt = 0; mt < 4; mt++) {
                const int r0 = wm * 64 + mt * 16;
                af[mt][0] = cvt_tf32(a[(r0 + g) * BKP2 + k0 + tg]);
                af[mt][1] = cvt_tf32(a[(r0 + g + 8) * BKP2 + k0 + tg]);
                af[mt][2] = cvt_tf32(a[(r0 + g) * BKP2 + k0 + tg + 4]);
                af[mt][3] = cvt_tf32(a[(r0 + g + 8) * BKP2 + k0 + tg + 4]);
            }
            uint32_t bf[4][2];
#pragma unroll
            for (int nt = 0; nt < 4; nt++) {
                const int r0 = wn * 32 + nt * 8;
                bf[nt][0] = cvt_tf32(bsh[(r0 + g) * BKP2 + k0 + tg]);
                bf[nt][1] = cvt_tf32(bsh[(r0 + g) * BKP2 + k0 + tg + 4]);
            }
#pragma unroll
            for (int mt = 0; mt < 4; mt++)
#pragma unroll
                for (int nt = 0; nt < 4; nt++)
                    mma_tf32(c[mt * 4 + nt],
                             af[mt][0], af[mt][1], af[mt][2], af[mt][3],
                             bf[nt][0], bf[nt][1]);
        }
    }

#pragma unroll
    for (int mt = 0; mt < 4; mt++) {
        const int row0 = bm + wm * 64 + mt * 16 + g;
#pragma unroll
        for (int nt = 0; nt < 4; nt++) {
            const int col = bn + wn * 32 + nt * 8 + tg * 2;
            float b0 = 0.f, b1 = 0.f;
            if (bias) { b0 = bias[col]; b1 = bias[col + 1]; }
            float2 v0 = make_float2(c[mt * 4 + nt][0] + b0, c[mt * 4 + nt][1] + b1);
            float2 v1 = make_float2(c[mt * 4 + nt][2] + b0, c[mt * 4 + nt][3] + b1);
            *(float2*)(C + (size_t)row0 * N + col) = v0;
            *(float2*)(C + (size_t)(row0 + 8) * N + col) = v1;
        }
    }
}

// ---------------------------------------------------------------------------
// Flash attention on mma.sync tf32 with 2-stage cp.async KV pipeline.
// grid (8 qtiles, 16 heads, 8 batch), 128 threads (4 warps).
// smem (u32): KVbuf0 [0,2304) KVbuf1 [2304,4608) P [4608,9216)
//             Q staging (phase A only) aliases [0,4608).
// K/V stored raw fp32; tf32 cvt at fragment read.
// ---------------------------------------------------------------------------
__global__ __launch_bounds__(128) void attn_mma(float* __restrict__ out)
{
    __shared__ uint32_t sm[9216];
    float* smf = (float*)sm;

    const int b = blockIdx.z;
    const int h = blockIdx.y;
    const int qt = blockIdx.x;
    const int t = threadIdx.x;
    const int w = t >> 5;
    const int lane = t & 31;
    const int g = lane >> 2;
    const int tg = lane & 3;
    const float scale = 0.17677669529663689f;  // 1/sqrt(32)
    const size_t base = (size_t)b * NTOK * C3;

    // ---- phase A: stage Q tile, build scaled tf32 A-fragments ----
#pragma unroll
    for (int i = 0; i < 8; i++) {
        const int e = i * 128 + t;        // 0..1023
        const int r = e >> 3;
        const int c4 = e & 7;
        float4 v = *(const float4*)(g_qkv + base + (size_t)(qt * 128 + r) * C3
                                    + h * HD + c4 * 4);
        float* p = smf + r * 36 + c4 * 4;
        p[0] = v.x; p[1] = v.y; p[2] = v.z; p[3] = v.w;
    }
    __syncthreads();

    uint32_t aq[2][4][4];
#pragma unroll
    for (int mt = 0; mt < 2; mt++) {
        const int r0 = w * 32 + mt * 16;
#pragma unroll
        for (int ks = 0; ks < 4; ks++) {
            aq[mt][ks][0] = cvt_tf32(smf[(r0 + g) * 36 + ks * 8 + tg] * scale);
            aq[mt][ks][1] = cvt_tf32(smf[(r0 + g + 8) * 36 + ks * 8 + tg] * scale);
            aq[mt][ks][2] = cvt_tf32(smf[(r0 + g) * 36 + ks * 8 + tg + 4] * scale);
            aq[mt][ks][3] = cvt_tf32(smf[(r0 + g + 8) * 36 + ks * 8 + tg + 4] * scale);
        }
    }
    __syncthreads();   // Q staging dead; KV buffers may now be written

    const uint32_t smb = smem_u32(sm);
    uint32_t* sP = sm + 4608 + w * 1152;

    // per-thread cp.async mapping for a 32-row KV tile: 2 (K,V) float4 pairs
    const int e0r = t >> 3;               // rows t/8 and t/8+16
    const int e0c = (t & 7) * 4;          // float col
    const float* kg = g_qkv + base + DIM + h * HD + e0c;
    const uint32_t kvo0 = (uint32_t)(e0r * 36 + e0c) * 4u;
    const uint32_t kvo1 = (uint32_t)((e0r + 16) * 36 + e0c) * 4u;
    const uint32_t vofs = 1152u * 4u;     // V region offset within a buf
    const uint32_t kvstride = 2304u * 4u; // buf stride

    // prefetch kt=0 -> buf0
    {
        const float* k0p = kg + (size_t)(e0r) * C3;
        const float* k1p = kg + (size_t)(e0r + 16) * C3;
        cp_async16(smb + kvo0, k0p);
        cp_async16(smb + vofs + kvo0, k0p + DIM);
        cp_async16(smb + kvo1, k1p);
        cp_async16(smb + vofs + kvo1, k1p + DIM);
    }
    cp_commit();

    float o[2][4][4];
#pragma unroll
    for (int mt = 0; mt < 2; mt++)
#pragma unroll
        for (int on = 0; on < 4; on++)
#pragma unroll
            for (int j = 0; j < 4; j++) o[mt][on][j] = 0.f;
    float mrow[2][2] = {{-1e30f, -1e30f}, {-1e30f, -1e30f}};
    float lrow[2][2] = {{0.f, 0.f}, {0.f, 0.f}};

    for (int kt = 0; kt < 32; kt++) {
        cp_wait0();
        __syncthreads();
        if (kt + 1 < 32) {
            const uint32_t bo = ((kt + 1) & 1) * kvstride;
            const float* k0p = kg + (size_t)((kt + 1) * 32 + e0r) * C3;
            const float* k1p = kg + (size_t)((kt + 1) * 32 + e0r + 16) * C3;
            cp_async16(smb + bo + kvo0, k0p);
            cp_async16(smb + bo + vofs + kvo0, k0p + DIM);
            cp_async16(smb + bo + kvo1, k1p);
            cp_async16(smb + bo + vofs + kvo1, k1p + DIM);
            cp_commit();
        }

        const float* fK = (const float*)(sm + (kt & 1) * 2304);
        const float* fV = fK + 1152;

        // ---- S = (Q*scale) K^T ----
        float s[2][4][4];
#pragma unroll
        for (int mt = 0; mt < 2; mt++)
#pragma unroll
            for (int nt = 0; nt < 4; nt++)
#pragma unroll
                for (int j = 0; j < 4; j++) s[mt][nt][j] = 0.f;

#pragma unroll
        for (int ks = 0; ks < 4; ks++) {
            uint32_t bk[4][2];
#pragma unroll
            for (int nt = 0; nt < 4; nt++) {
                bk[nt][0] = cvt_tf32(fK[(nt * 8 + g) * 36 + ks * 8 + tg]);
                bk[nt][1] = cvt_tf32(fK[(nt * 8 + g) * 36 + ks * 8 + tg + 4]);
            }
#pragma unroll
            for (int mt = 0; mt < 2; mt++)
#pragma unroll
                for (int nt = 0; nt < 4; nt++)
                    mma_tf32(s[mt][nt],
                             aq[mt][ks][0], aq[mt][ks][1],
                             aq[mt][ks][2], aq[mt][ks][3],
                             bk[nt][0], bk[nt][1]);
        }

        // ---- online softmax (per row-slot) ----
#pragma unroll
        for (int mt = 0; mt < 2; mt++) {
#pragma unroll
            for (int ri = 0; ri < 2; ri++) {
                float tmax = -1e30f;
#pragma unroll
                for (int nt = 0; nt < 4; nt++)
                    tmax = fmaxf(tmax, fmaxf(s[mt][nt][ri * 2], s[mt][nt][ri * 2 + 1]));
                tmax = fmaxf(tmax, __shfl_xor_sync(0xffffffffu, tmax, 1));
                tmax = fmaxf(tmax, __shfl_xor_sync(0xffffffffu, tmax, 2));
                const float mold = mrow[mt][ri];
                const float mnew = fmaxf(mold, tmax);
                const float alpha = __expf(mold - mnew);
                mrow[mt][ri] = mnew;
                float lsum = 0.f;
#pragma unroll
                for (int nt = 0; nt < 4; nt++) {
                    float p0 = __expf(s[mt][nt][ri * 2] - mnew);
                    float p1 = __expf(s[mt][nt][ri * 2 + 1] - mnew);
                    s[mt][nt][ri * 2] = p0;
                    s[mt][nt][ri * 2 + 1] = p1;
                    lsum += p0 + p1;
                }
                lrow[mt][ri] = lrow[mt][ri] * alpha + lsum;
#pragma unroll
                for (int on = 0; on < 4; on++) {
                    o[mt][on][ri * 2] *= alpha;
                    o[mt][on][ri * 2 + 1] *= alpha;
                }
            }
        }

        // ---- P -> per-warp smem (tf32) ----
#pragma unroll
        for (int mt = 0; mt < 2; mt++)
#pragma unroll
            for (int ri = 0; ri < 2; ri++) {
                const int row = mt * 16 + ri * 8 + g;
#pragma unroll
                for (int nt = 0; nt < 4; nt++) {
                    uint32_t* p = sP + row * 36 + nt * 8 + tg * 2;
                    p[0] = cvt_tf32(s[mt][nt][ri * 2]);
                    p[1] = cvt_tf32(s[mt][nt][ri * 2 + 1]);
                }
            }
        __syncwarp();

        // ---- O += P V ----
#pragma unroll
        for (int ks = 0; ks < 4; ks++) {
            uint32_t ap[2][4];
#pragma unroll
            for (int mt = 0; mt < 2; mt++) {
                ap[mt][0] = sP[(mt * 16 + g) * 36 + ks * 8 + tg];
                ap[mt][1] = sP[(mt * 16 + 8 + g) * 36 + ks * 8 + tg];
                ap[mt][2] = sP[(mt * 16 + g) * 36 + ks * 8 + tg + 4];
                ap[mt][3] = sP[(mt * 16 + 8 + g) * 36 + ks * 8 + tg + 4];
            }
            uint32_t bv[4][2];
#pragma unroll
            for (int on = 0; on < 4; on++) {
                bv[on][0] = cvt_tf32(fV[(ks * 8 + tg) * 36 + on * 8 + g]);
                bv[on][1] = cvt_tf32(fV[(ks * 8 + tg + 4) * 36 + on * 8 + g]);
            }
#pragma unroll
            for (int mt = 0; mt < 2; mt++)
#pragma unroll
                for (int on = 0; on < 4; on++)
                    mma_tf32(o[mt][on],
                             ap[mt][0], ap[mt][1], ap[mt][2], ap[mt][3],
                             bv[on][0], bv[on][1]);
        }
        __syncwarp();
    }

    // ---- epilogue: normalize and store ----
#pragma unroll
    for (int mt = 0; mt < 2; mt++)
#pragma unroll
        for (int ri = 0; ri < 2; ri++) {
            float l = lrow[mt][ri];
            l += __shfl_xor_sync(0xffffffffu, l, 1);
            l += __shfl_xor_sync(0xffffffffu, l, 2);
            const float inv = 1.f / l;
            const int qrow = qt * 128 + w * 32 + mt * 16 + ri * 8 + g;
            float* op = out + (size_t)(b * NTOK + qrow) * DIM + h * HD;
#pragma unroll
            for (int on = 0; on < 4; on++) {
                float2 v = make_float2(o[mt][on][ri * 2] * inv,
                                       o[mt][on][ri * 2 + 1] * inv);
                *(float2*)(op + on * 8 + tg * 2) = v;
            }
        }
}

// ---------------------------------------------------------------------------
// LePE 5x5 depthwise conv, added into attention output. (unchanged)
// ---------------------------------------------------------------------------
__global__ __launch_bounds__(512) void lepe_kernel(
    const float* __restrict__ x, const float* __restrict__ w,
    const float* __restrict__ bias, float* __restrict__ out)
{
    const int c = threadIdx.x;
    const int pix = blockIdx.x;
    const int b = pix >> 10;
    const int y = (pix >> 5) & 31;
    const int xx = pix & 31;

    float wreg[25];
#pragma unroll
    for (int i = 0; i < 25; i++) wreg[i] = w[c * 25 + i];

    float acc = bias[c];
#pragma unroll
    for (int dy = 0; dy < 5; dy++) {
        int yy = y + dy - 2;
        if (yy < 0 || yy > 31) continue;
#pragma unroll
        for (int dx = 0; dx < 5; dx++) {
            int xs = xx + dx - 2;
            if (xs < 0 || xs > 31) continue;
            acc = fmaf(x[((size_t)((b * 32 + yy) * 32 + xs)) * DIM + c],
                       wreg[dy * 5 + dx], acc);
        }
    }
    out[(size_t)pix * DIM + c] += acc;
}

// ---------------------------------------------------------------------------
extern "C" void kernel_launch(void* const* d_in, const int* in_sizes, int n_in,
                              void* d_out, int out_size)
{
    const float* x      = (const float*)d_in[0];
    const float* w_qkv  = (const float*)d_in[1];
    const float* w_proj = (const float*)d_in[2];
    const float* b_proj = (const float*)d_in[3];
    const float* w_lepe = (const float*)d_in[4];
    const float* b_lepe = (const float*)d_in[5];
    float* out = (float*)d_out;

    float *qkv_ptr = nullptr, *ao_ptr = nullptr;
    cudaGetSymbolAddress((void**)&qkv_ptr, g_qkv);
    cudaGetSymbolAddress((void**)&ao_ptr, g_ao);

    // 1) qkv = x @ w_qkv^T  (mma.sync tf32, cp.async pipeline)
    {
        dim3 grid(C3 / 128, M_ROWS / 128);
        gemm_mma<<<grid, 256>>>(x, w_qkv, nullptr, qkv_ptr, C3, DIM);
    }
    // 2) attention -> g_ao  (mma.sync tf32 flash, cp.async pipeline)
    {
        dim3 grid(NTOK / 128, NHEADS, BATCH);
        attn_mma<<<grid, 128>>>(ao_ptr);
    }
    // 3) g_ao += lepe(x)
    {
        lepe_kernel<<<BATCH * HH * WW, DIM>>>(x, w_lepe, b_lepe, ao_ptr);
    }
    // 4) out = g_ao @ w_proj^T + b_proj  (mma.sync tf32, cp.async pipeline)
    {
        dim3 grid(DIM / 128, M_ROWS / 128);
        gemm_mma<<<grid, 256>>>(ao_ptr, w_proj, b_proj, out, DIM, DIM);
    }
}

// round 13
// speedup vs baseline: 1.0563x; 1.0563x over previous
#include <cuda_runtime.h>
#include <cuda_bf16.h>
#include <cstdint>
#include <cstddef>

// ---------------------------------------------------------------------------
// AttentionLePE: x[8,32,32,512] -> qkv GEMM -> 16-head attention (d=32)
//                + 5x5 depthwise conv (LePE) -> proj GEMM + bias
// Round 12: revert to R10 structure (LDG fill keeps L1 reuse of weights —
// cp.async.cg's L1 bypass caused the R11 regression), add register prefetch
// of the next chunk/tile to overlap global latency with the MMA loop.
// ---------------------------------------------------------------------------

#define BATCH 8
#define HH 32
#define WW 32
#define DIM 512
#define NHEADS 16
#define HD 32
#define NTOK 1024              // HH*WW
#define M_ROWS (BATCH * NTOK)  // 8192
#define C3 (3 * DIM)           // 1536

__device__ float g_qkv[(size_t)M_ROWS * C3];   // 50.3 MB
__device__ float g_ao[(size_t)M_ROWS * DIM];   // 16.8 MB (attn out + lepe)

__device__ __forceinline__ uint32_t cvt_tf32(float f) {
    uint32_t r;
    asm("cvt.rna.tf32.f32 %0, %1;" : "=r"(r) : "f"(f));
    return r;
}

__device__ __forceinline__ void mma_tf32(
    float c[4], uint32_t a0, uint32_t a1, uint32_t a2, uint32_t a3,
    uint32_t b0, uint32_t b1)
{
    asm volatile(
        "mma.sync.aligned.m16n8k8.row.col.f32.tf32.tf32.f32 "
        "{%0,%1,%2,%3}, {%4,%5,%6,%7}, {%8,%9}, {%0,%1,%2,%3};"
        : "+f"(c[0]), "+f"(c[1]), "+f"(c[2]), "+f"(c[3])
        : "r"(a0), "r"(a1), "r"(a2), "r"(a3), "r"(b0), "r"(b1));
}

// ---------------------------------------------------------------------------
// mma.sync tf32 TN GEMM: C[m][n] = sum_k A[m*K+k] * B[n*K+k] (+ bias[n])
// Block 128x128, BK=32, 8 warps (2x4), warp tile 64x32 (4x4 m16n8k8).
// Register prefetch of chunk ch+1 overlaps LDG latency with the MMA loop;
// smem single-buffered (stride 36 -> conflict-free fragment LDS).
// ---------------------------------------------------------------------------
#define BKP 36  // padded K stride in floats

__global__ __launch_bounds__(256) void gemm_mma(
    const float* __restrict__ A, const float* __restrict__ B,
    const float* __restrict__ bias, float* __restrict__ C,
    int N, int K)
{
    __shared__ uint32_t sA[128 * BKP];
    __shared__ uint32_t sB[128 * BKP];

    const int t = threadIdx.x;
    const int wid = t >> 5;
    const int lane = t & 31;
    const int wm = wid >> 2;        // 0..1  (warp row)
    const int wn = wid & 3;         // 0..3  (warp col)
    const int g = lane >> 2;        // groupID 0..7
    const int tg = lane & 3;        // thread-in-group 0..3
    const int bm = blockIdx.y * 128;
    const int bn = blockIdx.x * 128;

    float c[16][4];
#pragma unroll
    for (int i = 0; i < 16; i++)
#pragma unroll
        for (int j = 0; j < 4; j++) c[i][j] = 0.f;

    // fill mapping: 4 (A,B) float4 pairs per thread per chunk
    float4 pa[4], pb[4];
#pragma unroll
    for (int i = 0; i < 4; i++) {
        const int e = i * 256 + t;
        const int r = e >> 3;
        const int c4 = e & 7;
        pa[i] = *(const float4*)(A + (size_t)(bm + r) * K + c4 * 4);
        pb[i] = *(const float4*)(B + (size_t)(bn + r) * K + c4 * 4);
    }

    const int nchunk = K >> 5;      // K/32
    for (int ch = 0; ch < nchunk; ch++) {
        __syncthreads();            // previous compute done with smem
#pragma unroll
        for (int i = 0; i < 4; i++) {
            const int e = i * 256 + t;
            const int r = e >> 3;
            const int c4 = e & 7;
            uint32_t* qa = &sA[r * BKP + c4 * 4];
            uint32_t* qb = &sB[r * BKP + c4 * 4];
            qa[0] = cvt_tf32(pa[i].x); qa[1] = cvt_tf32(pa[i].y);
            qa[2] = cvt_tf32(pa[i].z); qa[3] = cvt_tf32(pa[i].w);
            qb[0] = cvt_tf32(pb[i].x); qb[1] = cvt_tf32(pb[i].y);
            qb[2] = cvt_tf32(pb[i].z); qb[3] = cvt_tf32(pb[i].w);
        }
        __syncthreads();

        // prefetch next chunk into registers (latency hidden by MMA loop)
        if (ch + 1 < nchunk) {
            const int kb = (ch + 1) << 5;
#pragma unroll
            for (int i = 0; i < 4; i++) {
                const int e = i * 256 + t;
                const int r = e >> 3;
                const int c4 = e & 7;
                pa[i] = *(const float4*)(A + (size_t)(bm + r) * K + kb + c4 * 4);
                pb[i] = *(const float4*)(B + (size_t)(bn + r) * K + kb + c4 * 4);
            }
        }

#pragma unroll
        for (int ks = 0; ks < 4; ks++) {
            const int k0 = ks * 8;
            uint32_t af[4][4];
#pragma unroll
            for (int mt = 0; mt < 4; mt++) {
                const int r0 = wm * 64 + mt * 16;
                af[mt][0] = sA[(r0 + g) * BKP + k0 + tg];
                af[mt][1] = sA[(r0 + g + 8) * BKP + k0 + tg];
                af[mt][2] = sA[(r0 + g) * BKP + k0 + tg + 4];
                af[mt][3] = sA[(r0 + g + 8) * BKP + k0 + tg + 4];
            }
            uint32_t bf[4][2];
#pragma unroll
            for (int nt = 0; nt < 4; nt++) {
                const int r0 = wn * 32 + nt * 8;
                bf[nt][0] = sB[(r0 + g) * BKP + k0 + tg];
                bf[nt][1] = sB[(r0 + g) * BKP + k0 + tg + 4];
            }
#pragma unroll
            for (int mt = 0; mt < 4; mt++)
#pragma unroll
                for (int nt = 0; nt < 4; nt++)
                    mma_tf32(c[mt * 4 + nt],
                             af[mt][0], af[mt][1], af[mt][2], af[mt][3],
                             bf[nt][0], bf[nt][1]);
        }
    }

#pragma unroll
    for (int mt = 0; mt < 4; mt++) {
        const int row0 = bm + wm * 64 + mt * 16 + g;
#pragma unroll
        for (int nt = 0; nt < 4; nt++) {
            const int col = bn + wn * 32 + nt * 8 + tg * 2;
            float b0 = 0.f, b1 = 0.f;
            if (bias) { b0 = bias[col]; b1 = bias[col + 1]; }
            float2 v0 = make_float2(c[mt * 4 + nt][0] + b0, c[mt * 4 + nt][1] + b1);
            float2 v1 = make_float2(c[mt * 4 + nt][2] + b0, c[mt * 4 + nt][3] + b1);
            *(float2*)(C + (size_t)row0 * N + col) = v0;
            *(float2*)(C + (size_t)(row0 + 8) * N + col) = v1;
        }
    }
}

// ---------------------------------------------------------------------------
// Flash attention on mma.sync tf32 (R10 structure + K/V register prefetch).
// grid (8 qtiles, 16 heads, 8 batch), 128 threads (4 warps).
// ---------------------------------------------------------------------------
__global__ __launch_bounds__(128) void attn_mma(float* __restrict__ out)
{
    // phase A: Q staging 128x36 floats (4608 u32)
    // phase B: sK 32x36 | sV 32x36 | sP 4 x 32x36  (6912 u32 = 27.6 KB)
    __shared__ uint32_t sm[6912];
    float* smf = (float*)sm;

    const int b = blockIdx.z;
    const int h = blockIdx.y;
    const int qt = blockIdx.x;
    const int t = threadIdx.x;
    const int w = t >> 5;
    const int lane = t & 31;
    const int g = lane >> 2;
    const int tg = lane & 3;
    const float scale = 0.17677669529663689f;  // 1/sqrt(32)
    const size_t base = (size_t)b * NTOK * C3;

    // ---- phase A: stage Q tile, build scaled tf32 A-fragments ----
#pragma unroll
    for (int i = 0; i < 8; i++) {
        const int e = i * 128 + t;        // 0..1023
        const int r = e >> 3;
        const int c4 = e & 7;
        float4 v = *(const float4*)(g_qkv + base + (size_t)(qt * 128 + r) * C3
                                    + h * HD + c4 * 4);
        float* p = smf + r * 36 + c4 * 4;
        p[0] = v.x; p[1] = v.y; p[2] = v.z; p[3] = v.w;
    }
    __syncthreads();

    uint32_t aq[2][4][4];
#pragma unroll
    for (int mt = 0; mt < 2; mt++) {
        const int r0 = w * 32 + mt * 16;
#pragma unroll
        for (int ks = 0; ks < 4; ks++) {
            aq[mt][ks][0] = cvt_tf32(smf[(r0 + g) * 36 + ks * 8 + tg] * scale);
            aq[mt][ks][1] = cvt_tf32(smf[(r0 + g + 8) * 36 + ks * 8 + tg] * scale);
            aq[mt][ks][2] = cvt_tf32(smf[(r0 + g) * 36 + ks * 8 + tg + 4] * scale);
            aq[mt][ks][3] = cvt_tf32(smf[(r0 + g + 8) * 36 + ks * 8 + tg + 4] * scale);
        }
    }

    uint32_t* sK = sm;
    uint32_t* sV = sm + 1152;
    uint32_t* sP = sm + 2304 + w * 1152;

    // K/V load mapping: 2 (K,V) float4 pairs per thread per tile
    const int e0r = t >> 3;               // rows t/8 and t/8+16
    const int e0c = (t & 7) * 4;          // float col
    const float* kg = g_qkv + base + DIM + h * HD + e0c;

    float4 pk[2], pv[2];
    {
        const float* k0p = kg + (size_t)e0r * C3;
        const float* k1p = kg + (size_t)(e0r + 16) * C3;
        pk[0] = *(const float4*)k0p;       pv[0] = *(const float4*)(k0p + DIM);
        pk[1] = *(const float4*)k1p;       pv[1] = *(const float4*)(k1p + DIM);
    }

    float o[2][4][4];
#pragma unroll
    for (int mt = 0; mt < 2; mt++)
#pragma unroll
        for (int on = 0; on < 4; on++)
#pragma unroll
            for (int j = 0; j < 4; j++) o[mt][on][j] = 0.f;
    float mrow[2][2] = {{-1e30f, -1e30f}, {-1e30f, -1e30f}};
    float lrow[2][2] = {{0.f, 0.f}, {0.f, 0.f}};

    for (int kt = 0; kt < 32; kt++) {
        __syncthreads();   // previous iter (and phase A) done with sK/sV
        {
            uint32_t* q0 = sK + e0r * 36 + e0c;
            uint32_t* q1 = sK + (e0r + 16) * 36 + e0c;
            uint32_t* r0 = sV + e0r * 36 + e0c;
            uint32_t* r1 = sV + (e0r + 16) * 36 + e0c;
            q0[0] = cvt_tf32(pk[0].x); q0[1] = cvt_tf32(pk[0].y);
            q0[2] = cvt_tf32(pk[0].z); q0[3] = cvt_tf32(pk[0].w);
            q1[0] = cvt_tf32(pk[1].x); q1[1] = cvt_tf32(pk[1].y);
            q1[2] = cvt_tf32(pk[1].z); q1[3] = cvt_tf32(pk[1].w);
            r0[0] = cvt_tf32(pv[0].x); r0[1] = cvt_tf32(pv[0].y);
            r0[2] = cvt_tf32(pv[0].z); r0[3] = cvt_tf32(pv[0].w);
            r1[0] = cvt_tf32(pv[1].x); r1[1] = cvt_tf32(pv[1].y);
            r1[2] = cvt_tf32(pv[1].z); r1[3] = cvt_tf32(pv[1].w);
        }
        __syncthreads();

        // prefetch next K/V tile into registers
        if (kt + 1 < 32) {
            const float* k0p = kg + (size_t)((kt + 1) * 32 + e0r) * C3;
            const float* k1p = kg + (size_t)((kt + 1) * 32 + e0r + 16) * C3;
            pk[0] = *(const float4*)k0p;   pv[0] = *(const float4*)(k0p + DIM);
            pk[1] = *(const float4*)k1p;   pv[1] = *(const float4*)(k1p + DIM);
        }

        // ---- S = (Q*scale) K^T ----
        float s[2][4][4];
#pragma unroll
        for (int mt = 0; mt < 2; mt++)
#pragma unroll
            for (int nt = 0; nt < 4; nt++)
#pragma unroll
                for (int j = 0; j < 4; j++) s[mt][nt][j] = 0.f;

#pragma unroll
        for (int ks = 0; ks < 4; ks++) {
            uint32_t bk[4][2];
#pragma unroll
            for (int nt = 0; nt < 4; nt++) {
                bk[nt][0] = sK[(nt * 8 + g) * 36 + ks * 8 + tg];
                bk[nt][1] = sK[(nt * 8 + g) * 36 + ks * 8 + tg + 4];
            }
#pragma unroll
            for (int mt = 0; mt < 2; mt++)
#pragma unroll
                for (int nt = 0; nt < 4; nt++)
                    mma_tf32(s[mt][nt],
                             aq[mt][ks][0], aq[mt][ks][1],
                             aq[mt][ks][2], aq[mt][ks][3],
                             bk[nt][0], bk[nt][1]);
        }

        // ---- online softmax (per row-slot) ----
#pragma unroll
        for (int mt = 0; mt < 2; mt++) {
#pragma unroll
            for (int ri = 0; ri < 2; ri++) {
                float tmax = -1e30f;
#pragma unroll
                for (int nt = 0; nt < 4; nt++)
                    tmax = fmaxf(tmax, fmaxf(s[mt][nt][ri * 2], s[mt][nt][ri * 2 + 1]));
                tmax = fmaxf(tmax, __shfl_xor_sync(0xffffffffu, tmax, 1));
                tmax = fmaxf(tmax, __shfl_xor_sync(0xffffffffu, tmax, 2));
                const float mold = mrow[mt][ri];
                const float mnew = fmaxf(mold, tmax);
                const float alpha = __expf(mold - mnew);
                mrow[mt][ri] = mnew;
                float lsum = 0.f;
#pragma unroll
                for (int nt = 0; nt < 4; nt++) {
                    float p0 = __expf(s[mt][nt][ri * 2] - mnew);
                    float p1 = __expf(s[mt][nt][ri * 2 + 1] - mnew);
                    s[mt][nt][ri * 2] = p0;
                    s[mt][nt][ri * 2 + 1] = p1;
                    lsum += p0 + p1;
                }
                lrow[mt][ri] = lrow[mt][ri] * alpha + lsum;
#pragma unroll
                for (int on = 0; on < 4; on++) {
                    o[mt][on][ri * 2] *= alpha;
                    o[mt][on][ri * 2 + 1] *= alpha;
                }
            }
        }

        // ---- P -> per-warp smem (tf32), layout for A-fragment reads ----
#pragma unroll
        for (int mt = 0; mt < 2; mt++)
#pragma unroll
            for (int ri = 0; ri < 2; ri++) {
                const int row = mt * 16 + ri * 8 + g;
#pragma unroll
                for (int nt = 0; nt < 4; nt++) {
                    uint32_t* p = sP + row * 36 + nt * 8 + tg * 2;
                    p[0] = cvt_tf32(s[mt][nt][ri * 2]);
                    p[1] = cvt_tf32(s[mt][nt][ri * 2 + 1]);
                }
            }
        __syncwarp();

        // ---- O += P V ----
#pragma unroll
        for (int ks = 0; ks < 4; ks++) {
            uint32_t ap[2][4];
#pragma unroll
            for (int mt = 0; mt < 2; mt++) {
                ap[mt][0] = sP[(mt * 16 + g) * 36 + ks * 8 + tg];
                ap[mt][1] = sP[(mt * 16 + 8 + g) * 36 + ks * 8 + tg];
                ap[mt][2] = sP[(mt * 16 + g) * 36 + ks * 8 + tg + 4];
                ap[mt][3] = sP[(mt * 16 + 8 + g) * 36 + ks * 8 + tg + 4];
            }
            uint32_t bv[4][2];
#pragma unroll
            for (int on = 0; on < 4; on++) {
                bv[on][0] = sV[(ks * 8 + tg) * 36 + on * 8 + g];
                bv[on][1] = sV[(ks * 8 + tg + 4) * 36 + on * 8 + g];
            }
#pragma unroll
            for (int mt = 0; mt < 2; mt++)
#pragma unroll
                for (int on = 0; on < 4; on++)
                    mma_tf32(o[mt][on],
                             ap[mt][0], ap[mt][1], ap[mt][2], ap[mt][3],
                             bv[on][0], bv[on][1]);
        }
        __syncwarp();
    }

    // ---- epilogue: normalize and store ----
#pragma unroll
    for (int mt = 0; mt < 2; mt++)
#pragma unroll
        for (int ri = 0; ri < 2; ri++) {
            float l = lrow[mt][ri];
            l += __shfl_xor_sync(0xffffffffu, l, 1);
            l += __shfl_xor_sync(0xffffffffu, l, 2);
            const float inv = 1.f / l;
            const int qrow = qt * 128 + w * 32 + mt * 16 + ri * 8 + g;
            float* op = out + (size_t)(b * NTOK + qrow) * DIM + h * HD;
#pragma unroll
            for (int on = 0; on < 4; on++) {
                float2 v = make_float2(o[mt][on][ri * 2] * inv,
                                       o[mt][on][ri * 2 + 1] * inv);
                *(float2*)(op + on * 8 + tg * 2) = v;
            }
        }
}

// ---------------------------------------------------------------------------
// LePE 5x5 depthwise conv, added into attention output. (unchanged)
// ---------------------------------------------------------------------------
__global__ __launch_bounds__(512) void lepe_kernel(
    const float* __restrict__ x, const float* __restrict__ w,
    const float* __restrict__ bias, float* __restrict__ out)
{
    const int c = threadIdx.x;
    const int pix = blockIdx.x;
    const int b = pix >> 10;
    const int y = (pix >> 5) & 31;
    const int xx = pix & 31;

    float wreg[25];
#pragma unroll
    for (int i = 0; i < 25; i++) wreg[i] = w[c * 25 + i];

    float acc = bias[c];
#pragma unroll
    for (int dy = 0; dy < 5; dy++) {
        int yy = y + dy - 2;
        if (yy < 0 || yy > 31) continue;
#pragma unroll
        for (int dx = 0; dx < 5; dx++) {
            int xs = xx + dx - 2;
            if (xs < 0 || xs > 31) continue;
            acc = fmaf(x[((size_t)((b * 32 + yy) * 32 + xs)) * DIM + c],
                       wreg[dy * 5 + dx], acc);
        }
    }
    out[(size_t)pix * DIM + c] += acc;
}

// ---------------------------------------------------------------------------
extern "C" void kernel_launch(void* const* d_in, const int* in_sizes, int n_in,
                              void* d_out, int out_size)
{
    const float* x      = (const float*)d_in[0];
    const float* w_qkv  = (const float*)d_in[1];
    const float* w_proj = (const float*)d_in[2];
    const float* b_proj = (const float*)d_in[3];
    const float* w_lepe = (const float*)d_in[4];
    const float* b_lepe = (const float*)d_in[5];
    float* out = (float*)d_out;

    float *qkv_ptr = nullptr, *ao_ptr = nullptr;
    cudaGetSymbolAddress((void**)&qkv_ptr, g_qkv);
    cudaGetSymbolAddress((void**)&ao_ptr, g_ao);

    // 1) qkv = x @ w_qkv^T  (mma.sync tf32, reg prefetch)
    {
        dim3 grid(C3 / 128, M_ROWS / 128);
        gemm_mma<<<grid, 256>>>(x, w_qkv, nullptr, qkv_ptr, C3, DIM);
    }
    // 2) attention -> g_ao  (mma.sync tf32 flash, reg prefetch)
    {
        dim3 grid(NTOK / 128, NHEADS, BATCH);
        attn_mma<<<grid, 128>>>(ao_ptr);
    }
    // 3) g_ao += lepe(x)
    {
        lepe_kernel<<<BATCH * HH * WW, DIM>>>(x, w_lepe, b_lepe, ao_ptr);
    }
    // 4) out = g_ao @ w_proj^T + b_proj  (mma.sync tf32, reg prefetch)
    {
        dim3 grid(DIM / 128, M_ROWS / 128);
        gemm_mma<<<grid, 256>>>(ao_ptr, w_proj, b_proj, out, DIM, DIM);
    }
}

// round 14
// speedup vs baseline: 1.3359x; 1.2647x over previous
#include <cuda_runtime.h>
#include <cuda_bf16.h>
#include <cstdint>
#include <cstddef>

// ---------------------------------------------------------------------------
// AttentionLePE: x[8,32,32,512] -> qkv GEMM -> 16-head attention (d=32)
//                + 5x5 depthwise conv (LePE) -> proj GEMM + bias
// Round 13: best measured variant of each component —
//   GEMM  = R10 exact (LDG fill, L1 weight reuse, 38.9us proj)
//   attn  = R11 exact (cp.async KV double-buffer, 1 sync/iter, ~176us)
//   lepe  = new: 32 pixels/thread with 5x5 register sliding window
// ---------------------------------------------------------------------------

#define BATCH 8
#define HH 32
#define WW 32
#define DIM 512
#define NHEADS 16
#define HD 32
#define NTOK 1024              // HH*WW
#define M_ROWS (BATCH * NTOK)  // 8192
#define C3 (3 * DIM)           // 1536

__device__ float g_qkv[(size_t)M_ROWS * C3];   // 50.3 MB
__device__ float g_ao[(size_t)M_ROWS * DIM];   // 16.8 MB (attn out + lepe)

__device__ __forceinline__ uint32_t smem_u32(const void* p) {
    uint32_t a;
    asm("{ .reg .u64 t; cvta.to.shared.u64 t, %1; cvt.u32.u64 %0, t; }"
        : "=r"(a) : "l"(p));
    return a;
}

__device__ __forceinline__ void cp_async16(uint32_t saddr, const void* gaddr) {
    asm volatile("cp.async.cg.shared.global [%0], [%1], 16;"
                 :: "r"(saddr), "l"(gaddr));
}
__device__ __forceinline__ void cp_commit() {
    asm volatile("cp.async.commit_group;");
}
__device__ __forceinline__ void cp_wait0() {
    asm volatile("cp.async.wait_group 0;" ::: "memory");
}

__device__ __forceinline__ uint32_t cvt_tf32(float f) {
    uint32_t r;
    asm("cvt.rna.tf32.f32 %0, %1;" : "=r"(r) : "f"(f));
    return r;
}

__device__ __forceinline__ void mma_tf32(
    float c[4], uint32_t a0, uint32_t a1, uint32_t a2, uint32_t a3,
    uint32_t b0, uint32_t b1)
{
    asm volatile(
        "mma.sync.aligned.m16n8k8.row.col.f32.tf32.tf32.f32 "
        "{%0,%1,%2,%3}, {%4,%5,%6,%7}, {%8,%9}, {%0,%1,%2,%3};"
        : "+f"(c[0]), "+f"(c[1]), "+f"(c[2]), "+f"(c[3])
        : "r"(a0), "r"(a1), "r"(a2), "r"(a3), "r"(b0), "r"(b1));
}

// ---------------------------------------------------------------------------
// mma.sync tf32 TN GEMM (R10 exact): C[m][n] = sum_k A[m*K+k]*B[n*K+k] (+bias)
// Block 128x128, BK=32, 8 warps (2x4), warp tile 64x32 (4x4 m16n8k8).
// ---------------------------------------------------------------------------
#define BKP 36  // padded K stride in floats

__global__ __launch_bounds__(256) void gemm_mma(
    const float* __restrict__ A, const float* __restrict__ B,
    const float* __restrict__ bias, float* __restrict__ C,
    int N, int K)
{
    __shared__ uint32_t sA[128 * BKP];
    __shared__ uint32_t sB[128 * BKP];

    const int t = threadIdx.x;
    const int wid = t >> 5;
    const int lane = t & 31;
    const int wm = wid >> 2;        // 0..1  (warp row)
    const int wn = wid & 3;         // 0..3  (warp col)
    const int g = lane >> 2;        // groupID 0..7
    const int tg = lane & 3;        // thread-in-group 0..3
    const int bm = blockIdx.y * 128;
    const int bn = blockIdx.x * 128;

    float c[16][4];
#pragma unroll
    for (int i = 0; i < 16; i++)
#pragma unroll
        for (int j = 0; j < 4; j++) c[i][j] = 0.f;

    const int nchunk = K >> 5;      // K/32
    for (int ch = 0; ch < nchunk; ch++) {
        const int kbase = ch << 5;
        __syncthreads();
#pragma unroll
        for (int i = 0; i < 4; i++) {
            const int e = i * 256 + t;        // 0..1023
            const int r = e >> 3;             // row 0..127
            const int c4 = e & 7;             // float4 col 0..7
            float4 av = *(const float4*)(A + (size_t)(bm + r) * K + kbase + c4 * 4);
            float4 bv = *(const float4*)(B + (size_t)(bn + r) * K + kbase + c4 * 4);
            uint32_t* pa = &sA[r * BKP + c4 * 4];
            uint32_t* pb = &sB[r * BKP + c4 * 4];
            pa[0] = cvt_tf32(av.x); pa[1] = cvt_tf32(av.y);
            pa[2] = cvt_tf32(av.z); pa[3] = cvt_tf32(av.w);
            pb[0] = cvt_tf32(bv.x); pb[1] = cvt_tf32(bv.y);
            pb[2] = cvt_tf32(bv.z); pb[3] = cvt_tf32(bv.w);
        }
        __syncthreads();

#pragma unroll
        for (int ks = 0; ks < 4; ks++) {
            const int k0 = ks * 8;
            uint32_t af[4][4];
#pragma unroll
            for (int mt = 0; mt < 4; mt++) {
                const int r0 = wm * 64 + mt * 16;
                af[mt][0] = sA[(r0 + g) * BKP + k0 + tg];
                af[mt][1] = sA[(r0 + g + 8) * BKP + k0 + tg];
                af[mt][2] = sA[(r0 + g) * BKP + k0 + tg + 4];
                af[mt][3] = sA[(r0 + g + 8) * BKP + k0 + tg + 4];
            }
            uint32_t bf[4][2];
#pragma unroll
            for (int nt = 0; nt < 4; nt++) {
                const int r0 = wn * 32 + nt * 8;
                bf[nt][0] = sB[(r0 + g) * BKP + k0 + tg];
                bf[nt][1] = sB[(r0 + g) * BKP + k0 + tg + 4];
            }
#pragma unroll
            for (int mt = 0; mt < 4; mt++)
#pragma unroll
                for (int nt = 0; nt < 4; nt++)
                    mma_tf32(c[mt * 4 + nt],
                             af[mt][0], af[mt][1], af[mt][2], af[mt][3],
                             bf[nt][0], bf[nt][1]);
        }
    }

#pragma unroll
    for (int mt = 0; mt < 4; mt++) {
        const int row0 = bm + wm * 64 + mt * 16 + g;
#pragma unroll
        for (int nt = 0; nt < 4; nt++) {
            const int col = bn + wn * 32 + nt * 8 + tg * 2;
            float b0 = 0.f, b1 = 0.f;
            if (bias) { b0 = bias[col]; b1 = bias[col + 1]; }
            float2 v0 = make_float2(c[mt * 4 + nt][0] + b0, c[mt * 4 + nt][1] + b1);
            float2 v1 = make_float2(c[mt * 4 + nt][2] + b0, c[mt * 4 + nt][3] + b1);
            *(float2*)(C + (size_t)row0 * N + col) = v0;
            *(float2*)(C + (size_t)(row0 + 8) * N + col) = v1;
        }
    }
}

// ---------------------------------------------------------------------------
// Flash attention on mma.sync tf32 with 2-stage cp.async KV pipeline (R11).
// grid (8 qtiles, 16 heads, 8 batch), 128 threads (4 warps).
// smem (u32): KVbuf0 [0,2304) KVbuf1 [2304,4608) P [4608,9216)
//             Q staging (phase A only) aliases [0,4608).
// ---------------------------------------------------------------------------
__global__ __launch_bounds__(128) void attn_mma(float* __restrict__ out)
{
    __shared__ uint32_t sm[9216];
    float* smf = (float*)sm;

    const int b = blockIdx.z;
    const int h = blockIdx.y;
    const int qt = blockIdx.x;
    const int t = threadIdx.x;
    const int w = t >> 5;
    const int lane = t & 31;
    const int g = lane >> 2;
    const int tg = lane & 3;
    const float scale = 0.17677669529663689f;  // 1/sqrt(32)
    const size_t base = (size_t)b * NTOK * C3;

    // ---- phase A: stage Q tile, build scaled tf32 A-fragments ----
#pragma unroll
    for (int i = 0; i < 8; i++) {
        const int e = i * 128 + t;        // 0..1023
        const int r = e >> 3;
        const int c4 = e & 7;
        float4 v = *(const float4*)(g_qkv + base + (size_t)(qt * 128 + r) * C3
                                    + h * HD + c4 * 4);
        float* p = smf + r * 36 + c4 * 4;
        p[0] = v.x; p[1] = v.y; p[2] = v.z; p[3] = v.w;
    }
    __syncthreads();

    uint32_t aq[2][4][4];
#pragma unroll
    for (int mt = 0; mt < 2; mt++) {
        const int r0 = w * 32 + mt * 16;
#pragma unroll
        for (int ks = 0; ks < 4; ks++) {
            aq[mt][ks][0] = cvt_tf32(smf[(r0 + g) * 36 + ks * 8 + tg] * scale);
            aq[mt][ks][1] = cvt_tf32(smf[(r0 + g + 8) * 36 + ks * 8 + tg] * scale);
            aq[mt][ks][2] = cvt_tf32(smf[(r0 + g) * 36 + ks * 8 + tg + 4] * scale);
            aq[mt][ks][3] = cvt_tf32(smf[(r0 + g + 8) * 36 + ks * 8 + tg + 4] * scale);
        }
    }
    __syncthreads();   // Q staging dead; KV buffers may now be written

    const uint32_t smb = smem_u32(sm);
    uint32_t* sP = sm + 4608 + w * 1152;

    // per-thread cp.async mapping for a 32-row KV tile: 2 (K,V) float4 pairs
    const int e0r = t >> 3;               // rows t/8 and t/8+16
    const int e0c = (t & 7) * 4;          // float col
    const float* kg = g_qkv + base + DIM + h * HD + e0c;
    const uint32_t kvo0 = (uint32_t)(e0r * 36 + e0c) * 4u;
    const uint32_t kvo1 = (uint32_t)((e0r + 16) * 36 + e0c) * 4u;
    const uint32_t vofs = 1152u * 4u;     // V region offset within a buf
    const uint32_t kvstride = 2304u * 4u; // buf stride

    // prefetch kt=0 -> buf0
    {
        const float* k0p = kg + (size_t)(e0r) * C3;
        const float* k1p = kg + (size_t)(e0r + 16) * C3;
        cp_async16(smb + kvo0, k0p);
        cp_async16(smb + vofs + kvo0, k0p + DIM);
        cp_async16(smb + kvo1, k1p);
        cp_async16(smb + vofs + kvo1, k1p + DIM);
    }
    cp_commit();

    float o[2][4][4];
#pragma unroll
    for (int mt = 0; mt < 2; mt++)
#pragma unroll
        for (int on = 0; on < 4; on++)
#pragma unroll
            for (int j = 0; j < 4; j++) o[mt][on][j] = 0.f;
    float mrow[2][2] = {{-1e30f, -1e30f}, {-1e30f, -1e30f}};
    float lrow[2][2] = {{0.f, 0.f}, {0.f, 0.f}};

    for (int kt = 0; kt < 32; kt++) {
        cp_wait0();
        __syncthreads();
        if (kt + 1 < 32) {
            const uint32_t bo = ((kt + 1) & 1) * kvstride;
            const float* k0p = kg + (size_t)((kt + 1) * 32 + e0r) * C3;
            const float* k1p = kg + (size_t)((kt + 1) * 32 + e0r + 16) * C3;
            cp_async16(smb + bo + kvo0, k0p);
            cp_async16(smb + bo + vofs + kvo0, k0p + DIM);
            cp_async16(smb + bo + kvo1, k1p);
            cp_async16(smb + bo + vofs + kvo1, k1p + DIM);
            cp_commit();
        }

        const float* fK = (const float*)(sm + (kt & 1) * 2304);
        const float* fV = fK + 1152;

        // ---- S = (Q*scale) K^T ----
        float s[2][4][4];
#pragma unroll
        for (int mt = 0; mt < 2; mt++)
#pragma unroll
            for (int nt = 0; nt < 4; nt++)
#pragma unroll
                for (int j = 0; j < 4; j++) s[mt][nt][j] = 0.f;

#pragma unroll
        for (int ks = 0; ks < 4; ks++) {
            uint32_t bk[4][2];
#pragma unroll
            for (int nt = 0; nt < 4; nt++) {
                bk[nt][0] = cvt_tf32(fK[(nt * 8 + g) * 36 + ks * 8 + tg]);
                bk[nt][1] = cvt_tf32(fK[(nt * 8 + g) * 36 + ks * 8 + tg + 4]);
            }
#pragma unroll
            for (int mt = 0; mt < 2; mt++)
#pragma unroll
                for (int nt = 0; nt < 4; nt++)
                    mma_tf32(s[mt][nt],
                             aq[mt][ks][0], aq[mt][ks][1],
                             aq[mt][ks][2], aq[mt][ks][3],
                             bk[nt][0], bk[nt][1]);
        }

        // ---- online softmax (per row-slot) ----
#pragma unroll
        for (int mt = 0; mt < 2; mt++) {
#pragma unroll
            for (int ri = 0; ri < 2; ri++) {
                float tmax = -1e30f;
#pragma unroll
                for (int nt = 0; nt < 4; nt++)
                    tmax = fmaxf(tmax, fmaxf(s[mt][nt][ri * 2], s[mt][nt][ri * 2 + 1]));
                tmax = fmaxf(tmax, __shfl_xor_sync(0xffffffffu, tmax, 1));
                tmax = fmaxf(tmax, __shfl_xor_sync(0xffffffffu, tmax, 2));
                const float mold = mrow[mt][ri];
                const float mnew = fmaxf(mold, tmax);
                const float alpha = __expf(mold - mnew);
                mrow[mt][ri] = mnew;
                float lsum = 0.f;
#pragma unroll
                for (int nt = 0; nt < 4; nt++) {
                    float p0 = __expf(s[mt][nt][ri * 2] - mnew);
                    float p1 = __expf(s[mt][nt][ri * 2 + 1] - mnew);
                    s[mt][nt][ri * 2] = p0;
                    s[mt][nt][ri * 2 + 1] = p1;
                    lsum += p0 + p1;
                }
                lrow[mt][ri] = lrow[mt][ri] * alpha + lsum;
#pragma unroll
                for (int on = 0; on < 4; on++) {
                    o[mt][on][ri * 2] *= alpha;
                    o[mt][on][ri * 2 + 1] *= alpha;
                }
            }
        }

        // ---- P -> per-warp smem (tf32) ----
#pragma unroll
        for (int mt = 0; mt < 2; mt++)
#pragma unroll
            for (int ri = 0; ri < 2; ri++) {
                const int row = mt * 16 + ri * 8 + g;
#pragma unroll
                for (int nt = 0; nt < 4; nt++) {
                    uint32_t* p = sP + row * 36 + nt * 8 + tg * 2;
                    p[0] = cvt_tf32(s[mt][nt][ri * 2]);
                    p[1] = cvt_tf32(s[mt][nt][ri * 2 + 1]);
                }
            }
        __syncwarp();

        // ---- O += P V ----
#pragma unroll
        for (int ks = 0; ks < 4; ks++) {
            uint32_t ap[2][4];
#pragma unroll
            for (int mt = 0; mt < 2; mt++) {
                ap[mt][0] = sP[(mt * 16 + g) * 36 + ks * 8 + tg];
                ap[mt][1] = sP[(mt * 16 + 8 + g) * 36 + ks * 8 + tg];
                ap[mt][2] = sP[(mt * 16 + g) * 36 + ks * 8 + tg + 4];
                ap[mt][3] = sP[(mt * 16 + 8 + g) * 36 + ks * 8 + tg + 4];
            }
            uint32_t bv[4][2];
#pragma unroll
            for (int on = 0; on < 4; on++) {
                bv[on][0] = cvt_tf32(fV[(ks * 8 + tg) * 36 + on * 8 + g]);
                bv[on][1] = cvt_tf32(fV[(ks * 8 + tg + 4) * 36 + on * 8 + g]);
            }
#pragma unroll
            for (int mt = 0; mt < 2; mt++)
#pragma unroll
                for (int on = 0; on < 4; on++)
                    mma_tf32(o[mt][on],
                             ap[mt][0], ap[mt][1], ap[mt][2], ap[mt][3],
                             bv[on][0], bv[on][1]);
        }
        __syncwarp();
    }

    // ---- epilogue: normalize and store ----
#pragma unroll
    for (int mt = 0; mt < 2; mt++)
#pragma unroll
        for (int ri = 0; ri < 2; ri++) {
            float l = lrow[mt][ri];
            l += __shfl_xor_sync(0xffffffffu, l, 1);
            l += __shfl_xor_sync(0xffffffffu, l, 2);
            const float inv = 1.f / l;
            const int qrow = qt * 128 + w * 32 + mt * 16 + ri * 8 + g;
            float* op = out + (size_t)(b * NTOK + qrow) * DIM + h * HD;
#pragma unroll
            for (int on = 0; on < 4; on++) {
                float2 v = make_float2(o[mt][on][ri * 2] * inv,
                                       o[mt][on][ri * 2 + 1] * inv);
                *(float2*)(op + on * 8 + tg * 2) = v;
            }
        }
}

// ---------------------------------------------------------------------------
// LePE 5x5 depthwise conv, added into attention output.
// Block = (batch, row): 256 blocks x 512 threads (thread = channel).
// Each thread computes all 32 pixels of its row via a 5x5 register sliding
// window: weights loaded once, x loads cut 5x vs the per-pixel version.
// ---------------------------------------------------------------------------
__global__ __launch_bounds__(512) void lepe_kernel(
    const float* __restrict__ x, const float* __restrict__ w,
    const float* __restrict__ bias, float* __restrict__ out)
{
    const int c = threadIdx.x;
    const int b = blockIdx.x >> 5;
    const int y = blockIdx.x & 31;

    float wreg[25];
#pragma unroll
    for (int i = 0; i < 25; i++) wreg[i] = w[c * 25 + i];
    const float bi = bias[c];

    const float* xb = x + (size_t)b * 1024 * DIM + c;   // [y][x] indexed
    float* ob = out + (size_t)(b * 1024 + y * 32) * DIM + c;

    // row validity per dy
    bool rv[5];
    int yoff[5];
#pragma unroll
    for (int dy = 0; dy < 5; dy++) {
        const int yy = y + dy - 2;
        rv[dy] = (yy >= 0) && (yy < 32);
        yoff[dy] = yy * 32;
    }

    // init window for xx=0: cols -2..2 -> j=0..4 (col = j-2)
    float xw[5][5];
#pragma unroll
    for (int dy = 0; dy < 5; dy++)
#pragma unroll
        for (int j = 0; j < 5; j++) {
            const int col = j - 2;
            xw[dy][j] = (rv[dy] && col >= 0)
                        ? xb[(size_t)(yoff[dy] + col) * DIM] : 0.f;
        }

#pragma unroll
    for (int xx = 0; xx < 32; xx++) {
        float acc = bi;
#pragma unroll
        for (int dy = 0; dy < 5; dy++)
#pragma unroll
            for (int dx = 0; dx < 5; dx++)
                acc = fmaf(xw[dy][dx], wreg[dy * 5 + dx], acc);
        ob[(size_t)xx * DIM] += acc;

        if (xx < 31) {
            const int ncol = xx + 3;
            const bool cvld = (ncol < 32);
#pragma unroll
            for (int dy = 0; dy < 5; dy++) {
                const float nv = (rv[dy] && cvld)
                                 ? xb[(size_t)(yoff[dy] + ncol) * DIM] : 0.f;
#pragma unroll
                for (int j = 0; j < 4; j++) xw[dy][j] = xw[dy][j + 1];
                xw[dy][4] = nv;
            }
        }
    }
}

// ---------------------------------------------------------------------------
extern "C" void kernel_launch(void* const* d_in, const int* in_sizes, int n_in,
                              void* d_out, int out_size)
{
    const float* x      = (const float*)d_in[0];
    const float* w_qkv  = (const float*)d_in[1];
    const float* w_proj = (const float*)d_in[2];
    const float* b_proj = (const float*)d_in[3];
    const float* w_lepe = (const float*)d_in[4];
    const float* b_lepe = (const float*)d_in[5];
    float* out = (float*)d_out;

    float *qkv_ptr = nullptr, *ao_ptr = nullptr;
    cudaGetSymbolAddress((void**)&qkv_ptr, g_qkv);
    cudaGetSymbolAddress((void**)&ao_ptr, g_ao);

    // 1) qkv = x @ w_qkv^T  (mma.sync tf32, R10 fill)
    {
        dim3 grid(C3 / 128, M_ROWS / 128);
        gemm_mma<<<grid, 256>>>(x, w_qkv, nullptr, qkv_ptr, C3, DIM);
    }
    // 2) attention -> g_ao  (mma.sync tf32 flash, cp.async KV pipeline)
    {
        dim3 grid(NTOK / 128, NHEADS, BATCH);
        attn_mma<<<grid, 128>>>(ao_ptr);
    }
    // 3) g_ao += lepe(x)  (sliding-window depthwise conv)
    {
        lepe_kernel<<<BATCH * HH, DIM>>>(x, w_lepe, b_lepe, ao_ptr);
    }
    // 4) out = g_ao @ w_proj^T + b_proj  (mma.sync tf32, R10 fill)
    {
        dim3 grid(DIM / 128, M_ROWS / 128);
        gemm_mma<<<grid, 256>>>(ao_ptr, w_proj, b_proj, out, DIM, DIM);
    }
}